// round 5
// baseline (speedup 1.0000x reference)
#include <cuda_runtime.h>
#include <math.h>

#define BB 8
#define LL 48000
#define VV 28
#define QQ 256
#define CC 256
#define TT 960          // L / 50
#define NGD 29          // V + 1

#define ENC_BLOCKS 240
#define TR_BLOCKS  256
#define LOSS_BLOCKS 375         // 384000 / (256*4)

// ---------------- scratch ----------------
__device__ int    g_preds[BB * TT];
__device__ float  g_Wd2T[10 * 256 * 256];     // [j][c][q]
__device__ float  g_M[NGD * 5 * 10 * 256];    // logprob table: acc + bd2 - LSE
__device__ double g_prec[LOSS_BLOCKS];
__device__ double g_pkl[LOSS_BLOCKS];
__device__ int    g_ticket;                   // zero-init; self-resets each pass

// ---------------- f32x2 helpers ----------------
__device__ __forceinline__ void fma2(unsigned long long& d, unsigned long long a,
                                     unsigned long long b, unsigned long long c) {
    asm("fma.rn.f32x2 %0, %1, %2, %3;" : "=l"(d) : "l"(a), "l"(b), "l"(c));
}
__device__ __forceinline__ void add2(unsigned long long& d, unsigned long long a,
                                     unsigned long long b) {
    asm("add.rn.f32x2 %0, %1, %2;" : "=l"(d) : "l"(a), "l"(b));
}
__device__ __forceinline__ unsigned long long bcast2(float v) {
    unsigned long long r;
    asm("mov.b64 %0, {%1, %1};" : "=l"(r) : "f"(v));
    return r;
}
__device__ __forceinline__ void unpack2(unsigned long long v, float& lo, float& hi) {
    asm("mov.b64 {%0, %1}, %2;" : "=f"(lo), "=f"(hi) : "l"(v));
}

// ---------------- fused encoder + Wd2 transpose ----------------
// blocks [0,240): encoder, 32 t each (8 b * 30 chunks), 256 thr = 32 t x 8 cg
// blocks [240,496): Wd2 transpose (C,Q,K1) -> [j][c][q], one c per block
#define W2STRIDE 140
#define W1STRIDE 14
#define W2S_OFF 0
#define W1S_OFF (256 * W2STRIDE)
#define XS_OFF  (W1S_OFF + 256 * W1STRIDE)
#define B1S_OFF (XS_OFF + 32 * 50)
#define B2S_OFF (B1S_OFF + 256)
#define ENC_SMEM_FLOATS (B2S_OFF + 32)
#define ENC_SMEM_BYTES  (ENC_SMEM_FLOATS * 4)

__global__ __launch_bounds__(256, 1)
void k_enc_tr(const float* __restrict__ x, const float* __restrict__ gumbel,
              const float* __restrict__ W1, const float* __restrict__ b1,
              const float* __restrict__ W2, const float* __restrict__ b2,
              const float* __restrict__ Wd2)
{
    extern __shared__ float sm[];
    const int tid = threadIdx.x;

    if (blockIdx.x >= ENC_BLOCKS) {
        // ----- transpose branch -----
        const int c = blockIdx.x - ENC_BLOCKS;
        float* tile = sm;
        for (int lin = tid; lin < 2560; lin += 256)
            tile[lin] = Wd2[c * 2560 + lin];        // coalesced read
        __syncthreads();
        const int q = tid;
#pragma unroll
        for (int j = 0; j < 10; j++)
            g_Wd2T[j * 65536 + c * 256 + q] = tile[q * 10 + j];  // coalesced write
        return;
    }

    // ----- encoder branch -----
    float* W2s = sm + W2S_OFF;
    float* W1s = sm + W1S_OFF;
    float* xs  = sm + XS_OFF;
    float* b1s = sm + B1S_OFF;
    float* b2s = sm + B2S_OFF;

    const int b   = blockIdx.x / 30;
    const int t0  = (blockIdx.x % 30) * 32;

    for (int lin = tid; lin < 28 * 256 * 5; lin += 256) {
        int o = lin / 1280, rem = lin % 1280;
        int c = rem / 5,    kk  = rem % 5;
        W2s[c * W2STRIDE + kk * 28 + o] = W2[lin];
    }
    for (int lin = tid; lin < 2560; lin += 256)
        W1s[(lin / 10) * W1STRIDE + (lin % 10)] = W1[lin];
    for (int lin = tid; lin < 32 * 50; lin += 256)
        xs[lin] = x[b * LL + t0 * 50 + lin];
    b1s[tid] = b1[tid];
    if (tid < 28) b2s[tid] = b2[tid];
    __syncthreads();

    const int tl = tid >> 3;      // local t (0..31)
    const int cg = tid & 7;       // channel group (0..7)
    const int t  = t0 + tl;

    const unsigned long long* xs2 = (const unsigned long long*)(xs + tl * 50);
    unsigned long long xr2[25];
#pragma unroll
    for (int j = 0; j < 25; j++) xr2[j] = xs2[j];

    unsigned long long acc2[14];
#pragma unroll
    for (int j = 0; j < 14; j++) acc2[j] = 0ULL;

#pragma unroll 2
    for (int ci = 0; ci < 32; ci++) {
        const int c = cg + 8 * ci;
        const unsigned long long* w1p = (const unsigned long long*)(W1s + c * W1STRIDE);
        const float b1c = b1s[c];
        float h[5];
#pragma unroll
        for (int kk = 0; kk < 5; kk++) {
            unsigned long long s2 = 0ULL;
#pragma unroll
            for (int k2 = 0; k2 < 5; k2++)
                fma2(s2, xr2[kk * 5 + k2], w1p[k2], s2);
            float lo, hi; unpack2(s2, lo, hi);
            float s = lo + hi + b1c;
            h[kk] = fminf(fmaxf(s, 0.f), 6.f);
        }
        const float* wrow = &W2s[c * W2STRIDE];
#pragma unroll
        for (int kk = 0; kk < 5; kk++) {
            const unsigned long long hp = bcast2(h[kk]);
#pragma unroll
            for (int og = 0; og < 7; og++) {
                ulonglong2 w = *(const ulonglong2*)(wrow + kk * 28 + og * 4);
                fma2(acc2[og * 2 + 0], hp, w.x, acc2[og * 2 + 0]);
                fma2(acc2[og * 2 + 1], hp, w.y, acc2[og * 2 + 1]);
            }
        }
    }

#pragma unroll
    for (int j = 0; j < 14; j++) {
        unsigned long long v = acc2[j], o;
        o = __shfl_xor_sync(0xffffffffu, v, 1); add2(v, v, o);
        o = __shfl_xor_sync(0xffffffffu, v, 2); add2(v, v, o);
        o = __shfl_xor_sync(0xffffffffu, v, 4); add2(v, v, o);
        acc2[j] = v;
    }

    if (cg == 0) {
        float acc[28];
#pragma unroll
        for (int j = 0; j < 14; j++) unpack2(acc2[j], acc[2 * j], acc[2 * j + 1]);
        const float* g = gumbel + (b * TT + t) * VV;
        float best = -1e30f; int bi = 0;
#pragma unroll
        for (int o = 0; o < 28; o++) {
            float v = acc[o] + b2s[o] + g[o];
            if (v > best) { best = v; bi = o; }
        }
        g_preds[b * TT + t] = bi;
    }
}

// ---------------- decoder table: logprob[i][j2][j][q] ----------------
__global__ __launch_bounds__(256)
void k_table(const float* __restrict__ Wd1, const float* __restrict__ bd1,
             const float* __restrict__ bd2)
{
    __shared__ float rv[5 * 256];
    __shared__ float red[8];
    const int i   = blockIdx.x / 10;
    const int j   = blockIdx.x % 10;
    const int tid = threadIdx.x;

    for (int lin = tid; lin < 1280; lin += 256) {
        int c = lin / 5, j2 = lin % 5;
        float w = (i < VV) ? Wd1[i * 1280 + lin] : 0.f;
        rv[j2 * 256 + c] = fminf(fmaxf(w + bd1[c], 0.f), 6.f);
    }
    __syncthreads();

    float acc[5] = {0.f, 0.f, 0.f, 0.f, 0.f};
    const float* wt = g_Wd2T + j * 65536 + tid;
#pragma unroll 16
    for (int c = 0; c < 256; c++) {
        float w = wt[c * 256];
#pragma unroll
        for (int j2 = 0; j2 < 5; j2++)
            acc[j2] += rv[j2 * 256 + c] * w;
    }

    const float bdq  = bd2[tid];
    const int   lane = tid & 31, wid = tid >> 5;
    for (int j2 = 0; j2 < 5; j2++) {
        float v = acc[j2] + bdq;
        float m = v;
        for (int s = 16; s > 0; s >>= 1) m = fmaxf(m, __shfl_xor_sync(0xffffffffu, m, s));
        if (lane == 0) red[wid] = m;
        __syncthreads();
        float mAll = red[0];
#pragma unroll
        for (int w2 = 1; w2 < 8; w2++) mAll = fmaxf(mAll, red[w2]);
        __syncthreads();
        float e = expf(v - mAll);
        for (int s = 16; s > 0; s >>= 1) e += __shfl_xor_sync(0xffffffffu, e, s);
        if (lane == 0) red[wid] = e;
        __syncthreads();
        float ssum = 0.f;
#pragma unroll
        for (int w2 = 0; w2 < 8; w2++) ssum += red[w2];
        const float lse = mAll + logf(ssum);
        g_M[(((i * 5 + j2) * 10 + j) * 256) + tid] = v - lse;
        __syncthreads();
    }
}

// ---------------- loss (4 samples/thread) + fused final reduction ----------------
__global__ __launch_bounds__(256)
void k_loss(const float* __restrict__ x, const int* __restrict__ x_sl,
            const float* __restrict__ ngrams, float* __restrict__ out)
{
    __shared__ double sr[8], sk[8];
    __shared__ int    isLast;
    const int tid  = threadIdx.x;
    const int gid0 = (blockIdx.x * 256 + tid) * 4;      // < 384000
    const int b    = gid0 / LL;
    const int sl   = x_sl[b];
    const int zsl  = sl / 50;

    const float4 xv4 = *(const float4*)(x + gid0);
    const float xv[4] = {xv4.x, xv4.y, xv4.z, xv4.w};

    float rec = 0.f, kl = 0.f;
#pragma unroll
    for (int s = 0; s < 4; s++) {
        const int l = gid0 % LL + s;
        const int t = l / 50;
        if (l < sl) {
            float y = log1pf(255.f * fabsf(xv[s])) / 5.5451774444795625f;
            y = copysignf(y, xv[s]);
            int tq = (int)floorf((y + 1.0f) * 0.5f * 256.0f);
            tq = min(max(tq, 0), 255);
            const int j2 = (l / 10) % 5;
            const int j  = l % 10;
            const int i  = (t < zsl) ? g_preds[b * TT + t] : 28;
            rec -= g_M[(((i * 5 + j2) * 10 + j) * 256) + tq];
        }
        if ((l % 50) == 0 && t < zsl) {
            const int p  = g_preds[b * TT + t];
            const int a0 = (t >= 2) ? g_preds[b * TT + t - 2] : 28;
            const int a1 = (t >= 1) ? g_preds[b * TT + t - 1] : 28;
            const float pr = ngrams[(a0 * 29 + a1) * 28 + p];
            kl += logf(1.0f / (pr + 1e-10f) + 1e-10f);
        }
    }

    const int lane = tid & 31, wid = tid >> 5;
    for (int s = 16; s > 0; s >>= 1) {
        rec += __shfl_down_sync(0xffffffffu, rec, s);
        kl  += __shfl_down_sync(0xffffffffu, kl,  s);
    }
    if (lane == 0) { sr[wid] = (double)rec; sk[wid] = (double)kl; }
    __syncthreads();
    if (tid == 0) {
        double r = 0.0, k = 0.0;
#pragma unroll
        for (int w2 = 0; w2 < 8; w2++) { r += sr[w2]; k += sk[w2]; }
        g_prec[blockIdx.x] = r;
        g_pkl[blockIdx.x]  = k;
        __threadfence();
        int tck = atomicAdd(&g_ticket, 1);
        isLast = (tck == LOSS_BLOCKS - 1);
    }
    __syncthreads();

    if (isLast) {
        double r = 0.0, k = 0.0;
        for (int i = tid; i < LOSS_BLOCKS; i += 256) {
            r += __ldcg(&g_prec[i]);
            k += __ldcg(&g_pkl[i]);
        }
        for (int s = 16; s > 0; s >>= 1) {
            r += __shfl_down_sync(0xffffffffu, r, s);
            k += __shfl_down_sync(0xffffffffu, k, s);
        }
        __syncthreads();                 // sr/sk reuse
        if (lane == 0) { sr[wid] = r; sk[wid] = k; }
        __syncthreads();
        if (tid == 0) {
            double R = 0.0, K = 0.0;
#pragma unroll
            for (int w2 = 0; w2 < 8; w2++) { R += sr[w2]; K += sk[w2]; }
            long long sx = 0, sz = 0;
#pragma unroll
            for (int bb = 0; bb < BB; bb++) { sx += x_sl[bb]; sz += x_sl[bb] / 50; }
            out[0] = (float)(R / (double)sx + K / (double)sz);
            g_ticket = 0;               // self-reset for next graph replay
        }
    }
}

// ---------------- launch ----------------
extern "C" void kernel_launch(void* const* d_in, const int* in_sizes, int n_in,
                              void* d_out, int out_size)
{
    const float* x      = (const float*)d_in[0];
    const int*   x_sl   = (const int*)  d_in[1];
    const float* ngrams = (const float*)d_in[4];
    const float* gumbel = (const float*)d_in[5];
    const float* W1     = (const float*)d_in[6];
    const float* b1     = (const float*)d_in[7];
    const float* W2     = (const float*)d_in[8];
    const float* b2     = (const float*)d_in[9];
    const float* Wd1    = (const float*)d_in[10];
    const float* bd1    = (const float*)d_in[11];
    const float* Wd2    = (const float*)d_in[12];
    const float* bd2    = (const float*)d_in[13];
    float* out = (float*)d_out;

    cudaFuncSetAttribute(k_enc_tr, cudaFuncAttributeMaxDynamicSharedMemorySize,
                         ENC_SMEM_BYTES);

    k_enc_tr<<<ENC_BLOCKS + TR_BLOCKS, 256, ENC_SMEM_BYTES>>>(
        x, gumbel, W1, b1, W2, b2, Wd2);
    k_table<<<290, 256>>>(Wd1, bd1, bd2);
    k_loss<<<LOSS_BLOCKS, 256>>>(x, x_sl, ngrams, out);
}

// round 7
// speedup vs baseline: 1.1157x; 1.1157x over previous
#include <cuda_runtime.h>
#include <math.h>

#define BB 8
#define LL 48000
#define VV 28
#define QQ 256
#define CC 256
#define TT 960          // L / 50
#define NGD 29          // V + 1

#define ENC_BLOCKS 120          // 8 b * 15 chunks of 64 t
#define TR_BLOCKS  256
#define LOSS_BLOCKS 375         // 384000 / (256*4)

// ---------------- scratch ----------------
__device__ int    g_preds[BB * TT];
__device__ float  g_Wd2T[10 * 256 * 256];     // [j][c][q]
__device__ float  g_M[NGD * 5 * 10 * 256];    // logprob table: acc + bd2 - LSE
__device__ double g_prec[LOSS_BLOCKS];
__device__ double g_pkl[LOSS_BLOCKS];
__device__ int    g_ticket;                   // zero-init; self-resets each pass

// ---------------- f32x2 helpers ----------------
__device__ __forceinline__ void fma2(unsigned long long& d, unsigned long long a,
                                     unsigned long long b, unsigned long long c) {
    asm("fma.rn.f32x2 %0, %1, %2, %3;" : "=l"(d) : "l"(a), "l"(b), "l"(c));
}
__device__ __forceinline__ void add2(unsigned long long& d, unsigned long long a,
                                     unsigned long long b) {
    asm("add.rn.f32x2 %0, %1, %2;" : "=l"(d) : "l"(a), "l"(b));
}
__device__ __forceinline__ unsigned long long bcast2(float v) {
    unsigned long long r;
    asm("mov.b64 %0, {%1, %1};" : "=l"(r) : "f"(v));
    return r;
}
__device__ __forceinline__ void unpack2(unsigned long long v, float& lo, float& hi) {
    asm("mov.b64 {%0, %1}, %2;" : "=f"(lo), "=f"(hi) : "l"(v));
}

// ---------------- fused encoder + Wd2 transpose ----------------
// blocks [0,120): encoder, 64 t each, 512 thr = 64 t x 8 cg  (16 warps/SM, 1 wave)
// blocks [120,376): Wd2 transpose (C,Q,K1) -> [j][c][q], one c per block
#define W2STRIDE 140
#define W1STRIDE 14
#define ENC_T    64
#define W2S_OFF 0
#define W1S_OFF (256 * W2STRIDE)
#define XS_OFF  (W1S_OFF + 256 * W1STRIDE)
#define B1S_OFF (XS_OFF + ENC_T * 50)
#define B2S_OFF (B1S_OFF + 256)
#define ENC_SMEM_FLOATS (B2S_OFF + 32)
#define ENC_SMEM_BYTES  (ENC_SMEM_FLOATS * 4)

__global__ __launch_bounds__(512, 1)
void k_enc_tr(const float* __restrict__ x, const float* __restrict__ gumbel,
              const float* __restrict__ W1, const float* __restrict__ b1,
              const float* __restrict__ W2, const float* __restrict__ b2,
              const float* __restrict__ Wd2)
{
    extern __shared__ float sm[];
    const int tid = threadIdx.x;

    if (blockIdx.x >= ENC_BLOCKS) {
        // ----- transpose branch -----
        const int c = blockIdx.x - ENC_BLOCKS;
        float* tile = sm;
        for (int lin = tid; lin < 2560; lin += 512)
            tile[lin] = Wd2[c * 2560 + lin];        // coalesced read
        __syncthreads();
        if (tid < 256) {
            const int q = tid;
#pragma unroll
            for (int j = 0; j < 10; j++)
                g_Wd2T[j * 65536 + c * 256 + q] = tile[q * 10 + j];  // coalesced write
        }
        return;
    }

    // ----- encoder branch -----
    float* W2s = sm + W2S_OFF;
    float* W1s = sm + W1S_OFF;
    float* xs  = sm + XS_OFF;
    float* b1s = sm + B1S_OFF;
    float* b2s = sm + B2S_OFF;

    const int b   = blockIdx.x / 15;
    const int t0  = (blockIdx.x % 15) * ENC_T;

    for (int lin = tid; lin < 28 * 256 * 5; lin += 512) {
        int o = lin / 1280, rem = lin % 1280;
        int c = rem / 5,    kk  = rem % 5;
        W2s[c * W2STRIDE + kk * 28 + o] = W2[lin];
    }
    for (int lin = tid; lin < 2560; lin += 512)
        W1s[(lin / 10) * W1STRIDE + (lin % 10)] = W1[lin];
    for (int lin = tid; lin < ENC_T * 50; lin += 512)
        xs[lin] = x[b * LL + t0 * 50 + lin];
    if (tid < 256) b1s[tid] = b1[tid];
    if (tid < 28)  b2s[tid] = b2[tid];
    __syncthreads();

    const int tl = tid >> 3;      // local t (0..63)
    const int cg = tid & 7;       // channel group (0..7)
    const int t  = t0 + tl;

    const unsigned long long* xs2 = (const unsigned long long*)(xs + tl * 50);
    unsigned long long xr2[25];
#pragma unroll
    for (int j = 0; j < 25; j++) xr2[j] = xs2[j];

    unsigned long long acc2[14];
#pragma unroll
    for (int j = 0; j < 14; j++) acc2[j] = 0ULL;

#pragma unroll 2
    for (int ci = 0; ci < 32; ci++) {
        const int c = cg + 8 * ci;
        const unsigned long long* w1p = (const unsigned long long*)(W1s + c * W1STRIDE);
        const float b1c = b1s[c];
        float h[5];
#pragma unroll
        for (int kk = 0; kk < 5; kk++) {
            unsigned long long s2 = 0ULL;
#pragma unroll
            for (int k2 = 0; k2 < 5; k2++)
                fma2(s2, xr2[kk * 5 + k2], w1p[k2], s2);
            float lo, hi; unpack2(s2, lo, hi);
            float s = lo + hi + b1c;
            h[kk] = fminf(fmaxf(s, 0.f), 6.f);
        }
        const float* wrow = &W2s[c * W2STRIDE];
#pragma unroll
        for (int kk = 0; kk < 5; kk++) {
            const unsigned long long hp = bcast2(h[kk]);
#pragma unroll
            for (int og = 0; og < 7; og++) {
                ulonglong2 w = *(const ulonglong2*)(wrow + kk * 28 + og * 4);
                fma2(acc2[og * 2 + 0], hp, w.x, acc2[og * 2 + 0]);
                fma2(acc2[og * 2 + 1], hp, w.y, acc2[og * 2 + 1]);
            }
        }
    }

#pragma unroll
    for (int j = 0; j < 14; j++) {
        unsigned long long v = acc2[j], o;
        o = __shfl_xor_sync(0xffffffffu, v, 1); add2(v, v, o);
        o = __shfl_xor_sync(0xffffffffu, v, 2); add2(v, v, o);
        o = __shfl_xor_sync(0xffffffffu, v, 4); add2(v, v, o);
        acc2[j] = v;
    }

    if (cg == 0) {
        float acc[28];
#pragma unroll
        for (int j = 0; j < 14; j++) unpack2(acc2[j], acc[2 * j], acc[2 * j + 1]);
        const float* g = gumbel + (b * TT + t) * VV;
        float best = -1e30f; int bi = 0;
#pragma unroll
        for (int o = 0; o < 28; o++) {
            float v = acc[o] + b2s[o] + g[o];
            if (v > best) { best = v; bi = o; }
        }
        g_preds[b * TT + t] = bi;
    }
}

// ---------------- decoder table: logprob[i][j2][j][q] ----------------
__global__ __launch_bounds__(256)
void k_table(const float* __restrict__ Wd1, const float* __restrict__ bd1,
             const float* __restrict__ bd2)
{
    __shared__ float rv[5 * 256];
    __shared__ float red[8];
    const int i   = blockIdx.x / 10;
    const int j   = blockIdx.x % 10;
    const int tid = threadIdx.x;

    for (int lin = tid; lin < 1280; lin += 256) {
        int c = lin / 5, j2 = lin % 5;
        float w = (i < VV) ? Wd1[i * 1280 + lin] : 0.f;
        rv[j2 * 256 + c] = fminf(fmaxf(w + bd1[c], 0.f), 6.f);
    }
    __syncthreads();

    float acc[5] = {0.f, 0.f, 0.f, 0.f, 0.f};
    const float* wt = g_Wd2T + j * 65536 + tid;
#pragma unroll 16
    for (int c = 0; c < 256; c++) {
        float w = wt[c * 256];
#pragma unroll
        for (int j2 = 0; j2 < 5; j2++)
            acc[j2] += rv[j2 * 256 + c] * w;
    }

    const float bdq  = bd2[tid];
    const int   lane = tid & 31, wid = tid >> 5;
    for (int j2 = 0; j2 < 5; j2++) {
        float v = acc[j2] + bdq;
        float m = v;
        for (int s = 16; s > 0; s >>= 1) m = fmaxf(m, __shfl_xor_sync(0xffffffffu, m, s));
        if (lane == 0) red[wid] = m;
        __syncthreads();
        float mAll = red[0];
#pragma unroll
        for (int w2 = 1; w2 < 8; w2++) mAll = fmaxf(mAll, red[w2]);
        __syncthreads();
        float e = expf(v - mAll);
        for (int s = 16; s > 0; s >>= 1) e += __shfl_xor_sync(0xffffffffu, e, s);
        if (lane == 0) red[wid] = e;
        __syncthreads();
        float ssum = 0.f;
#pragma unroll
        for (int w2 = 0; w2 < 8; w2++) ssum += red[w2];
        const float lse = mAll + logf(ssum);
        g_M[(((i * 5 + j2) * 10 + j) * 256) + tid] = v - lse;
        __syncthreads();
    }
}

// ---------------- loss (4 samples/thread) + fused final reduction ----------------
__global__ __launch_bounds__(256)
void k_loss(const float* __restrict__ x, const int* __restrict__ x_sl,
            const float* __restrict__ ngrams, float* __restrict__ out)
{
    __shared__ double sr[8], sk[8];
    __shared__ int    isLast;
    const int tid  = threadIdx.x;
    const int gid0 = (blockIdx.x * 256 + tid) * 4;      // < 384000
    const int b    = gid0 / LL;
    const int sl   = x_sl[b];
    const int zsl  = sl / 50;

    const float4 xv4 = *(const float4*)(x + gid0);
    const float xv[4] = {xv4.x, xv4.y, xv4.z, xv4.w};

    float rec = 0.f, kl = 0.f;
#pragma unroll
    for (int s = 0; s < 4; s++) {
        const int l = gid0 % LL + s;
        const int t = l / 50;
        if (l < sl) {
            float y = log1pf(255.f * fabsf(xv[s])) / 5.5451774444795625f;
            y = copysignf(y, xv[s]);
            int tq = (int)floorf((y + 1.0f) * 0.5f * 256.0f);
            tq = min(max(tq, 0), 255);
            const int j2 = (l / 10) % 5;
            const int j  = l % 10;
            const int i  = (t < zsl) ? g_preds[b * TT + t] : 28;
            rec -= g_M[(((i * 5 + j2) * 10 + j) * 256) + tq];
        }
        if ((l % 50) == 0 && t < zsl) {
            const int p  = g_preds[b * TT + t];
            const int a0 = (t >= 2) ? g_preds[b * TT + t - 2] : 28;
            const int a1 = (t >= 1) ? g_preds[b * TT + t - 1] : 28;
            const float pr = ngrams[(a0 * 29 + a1) * 28 + p];
            kl += logf(1.0f / (pr + 1e-10f) + 1e-10f);
        }
    }

    const int lane = tid & 31, wid = tid >> 5;
    for (int s = 16; s > 0; s >>= 1) {
        rec += __shfl_down_sync(0xffffffffu, rec, s);
        kl  += __shfl_down_sync(0xffffffffu, kl,  s);
    }
    if (lane == 0) { sr[wid] = (double)rec; sk[wid] = (double)kl; }
    __syncthreads();
    if (tid == 0) {
        double r = 0.0, k = 0.0;
#pragma unroll
        for (int w2 = 0; w2 < 8; w2++) { r += sr[w2]; k += sk[w2]; }
        g_prec[blockIdx.x] = r;
        g_pkl[blockIdx.x]  = k;
        __threadfence();
        int tck = atomicAdd(&g_ticket, 1);
        isLast = (tck == LOSS_BLOCKS - 1);
    }
    __syncthreads();

    if (isLast) {
        double r = 0.0, k = 0.0;
        for (int i = tid; i < LOSS_BLOCKS; i += 256) {
            r += __ldcg(&g_prec[i]);
            k += __ldcg(&g_pkl[i]);
        }
        for (int s = 16; s > 0; s >>= 1) {
            r += __shfl_down_sync(0xffffffffu, r, s);
            k += __shfl_down_sync(0xffffffffu, k, s);
        }
        __syncthreads();                 // sr/sk reuse
        if (lane == 0) { sr[wid] = r; sk[wid] = k; }
        __syncthreads();
        if (tid == 0) {
            double R = 0.0, K = 0.0;
#pragma unroll
            for (int w2 = 0; w2 < 8; w2++) { R += sr[w2]; K += sk[w2]; }
            long long sx = 0, sz = 0;
#pragma unroll
            for (int bb = 0; bb < BB; bb++) { sx += x_sl[bb]; sz += x_sl[bb] / 50; }
            out[0] = (float)(R / (double)sx + K / (double)sz);
            g_ticket = 0;               // self-reset for next graph replay
        }
    }
}

// ---------------- launch ----------------
extern "C" void kernel_launch(void* const* d_in, const int* in_sizes, int n_in,
                              void* d_out, int out_size)
{
    const float* x      = (const float*)d_in[0];
    const int*   x_sl   = (const int*)  d_in[1];
    const float* ngrams = (const float*)d_in[4];
    const float* gumbel = (const float*)d_in[5];
    const float* W1     = (const float*)d_in[6];
    const float* b1     = (const float*)d_in[7];
    const float* W2     = (const float*)d_in[8];
    const float* b2     = (const float*)d_in[9];
    const float* Wd1    = (const float*)d_in[10];
    const float* bd1    = (const float*)d_in[11];
    const float* Wd2    = (const float*)d_in[12];
    const float* bd2    = (const float*)d_in[13];
    float* out = (float*)d_out;

    cudaFuncSetAttribute(k_enc_tr, cudaFuncAttributeMaxDynamicSharedMemorySize,
                         ENC_SMEM_BYTES);

    k_enc_tr<<<ENC_BLOCKS + TR_BLOCKS, 512, ENC_SMEM_BYTES>>>(
        x, gumbel, W1, b1, W2, b2, Wd2);
    k_table<<<290, 256>>>(Wd1, bd1, bd2);
    k_loss<<<LOSS_BLOCKS, 256>>>(x, x_sl, ngrams, out);
}

// round 8
// speedup vs baseline: 1.3630x; 1.2216x over previous
#include <cuda_runtime.h>
#include <math.h>

#define BB 8
#define LL 48000
#define VV 28
#define QQ 256
#define CC 256
#define TT 960          // L / 50
#define NGD 29          // V + 1

#define ENC_BLOCKS 120          // 8 b * 15 chunks of 64 t
#define TR_BLOCKS  256
#define LOSS_BLOCKS 375         // 384000 / (256*4)

// ---------------- scratch ----------------
__device__ int    g_preds[BB * TT];
__device__ float  g_Wd2T[10 * 256 * 256];     // [j][c][q]
__device__ float  g_M[NGD * 5 * 10 * 256];    // logprob table: acc + bd2 - LSE
__device__ double g_prec[LOSS_BLOCKS];
__device__ double g_pkl[LOSS_BLOCKS];
__device__ int    g_ticket;                   // zero-init; self-resets each pass

// ---------------- f32x2 helpers ----------------
__device__ __forceinline__ void fma2(unsigned long long& d, unsigned long long a,
                                     unsigned long long b, unsigned long long c) {
    asm("fma.rn.f32x2 %0, %1, %2, %3;" : "=l"(d) : "l"(a), "l"(b), "l"(c));
}
__device__ __forceinline__ void add2(unsigned long long& d, unsigned long long a,
                                     unsigned long long b) {
    asm("add.rn.f32x2 %0, %1, %2;" : "=l"(d) : "l"(a), "l"(b));
}
__device__ __forceinline__ unsigned long long bcast2(float v) {
    unsigned long long r;
    asm("mov.b64 %0, {%1, %1};" : "=l"(r) : "f"(v));
    return r;
}
__device__ __forceinline__ void unpack2(unsigned long long v, float& lo, float& hi) {
    asm("mov.b64 {%0, %1}, %2;" : "=f"(lo), "=f"(hi) : "l"(v));
}

// ---------------- fused encoder + Wd2 transpose ----------------
// blocks [0,120): encoder, 64 t each, 256 thr = 32 slots x 8 cg, 2 t per slot
//                 (register t-blocking: each W2 smem load feeds 8 t per warp)
// blocks [120,376): Wd2 transpose (C,Q,K1) -> [j][c][q], one c per block
#define W2STRIDE 140
#define W1STRIDE 14
#define ENC_T    64
#define W2S_OFF 0
#define W1S_OFF (256 * W2STRIDE)
#define XS_OFF  (W1S_OFF + 256 * W1STRIDE)
#define B1S_OFF (XS_OFF + ENC_T * 50)
#define B2S_OFF (B1S_OFF + 256)
#define ENC_SMEM_FLOATS (B2S_OFF + 32)
#define ENC_SMEM_BYTES  (ENC_SMEM_FLOATS * 4)

__global__ __launch_bounds__(256, 1)
void k_enc_tr(const float* __restrict__ x, const float* __restrict__ gumbel,
              const float* __restrict__ W1, const float* __restrict__ b1,
              const float* __restrict__ W2, const float* __restrict__ b2,
              const float* __restrict__ Wd2)
{
    extern __shared__ float sm[];
    const int tid = threadIdx.x;

    if (blockIdx.x >= ENC_BLOCKS) {
        // ----- transpose branch -----
        const int c = blockIdx.x - ENC_BLOCKS;
        float* tile = sm;
        for (int lin = tid; lin < 2560; lin += 256)
            tile[lin] = Wd2[c * 2560 + lin];        // coalesced read
        __syncthreads();
        const int q = tid;
#pragma unroll
        for (int j = 0; j < 10; j++)
            g_Wd2T[j * 65536 + c * 256 + q] = tile[q * 10 + j];  // coalesced write
        return;
    }

    // ----- encoder branch -----
    float* W2s = sm + W2S_OFF;
    float* W1s = sm + W1S_OFF;
    float* xs  = sm + XS_OFF;
    float* b1s = sm + B1S_OFF;
    float* b2s = sm + B2S_OFF;

    const int b   = blockIdx.x / 15;
    const int t0  = (blockIdx.x % 15) * ENC_T;

    for (int lin = tid; lin < 28 * 256 * 5; lin += 256) {
        int o = lin / 1280, rem = lin % 1280;
        int c = rem / 5,    kk  = rem % 5;
        W2s[c * W2STRIDE + kk * 28 + o] = W2[lin];
    }
    for (int lin = tid; lin < 2560; lin += 256)
        W1s[(lin / 10) * W1STRIDE + (lin % 10)] = W1[lin];
    for (int lin = tid; lin < ENC_T * 50; lin += 256)
        xs[lin] = x[b * LL + t0 * 50 + lin];
    b1s[tid] = b1[tid];
    if (tid < 28) b2s[tid] = b2[tid];
    __syncthreads();

    const int slot = tid >> 3;    // 0..31, each slot owns 2 consecutive t
    const int cg   = tid & 7;     // channel group (0..7)
    const int ta   = t0 + 2 * slot;

    // two x windows in registers (disjoint, 50 floats each, 8B-aligned)
    const unsigned long long* xsa = (const unsigned long long*)(xs + 100 * slot);
    const unsigned long long* xsb = (const unsigned long long*)(xs + 100 * slot + 50);
    unsigned long long xra[25], xrb[25];
#pragma unroll
    for (int j = 0; j < 25; j++) { xra[j] = xsa[j]; xrb[j] = xsb[j]; }

    unsigned long long acca[14], accb[14];
#pragma unroll
    for (int j = 0; j < 14; j++) { acca[j] = 0ULL; accb[j] = 0ULL; }

    for (int ci = 0; ci < 32; ci++) {
        const int c = cg + 8 * ci;
        const unsigned long long* w1p = (const unsigned long long*)(W1s + c * W1STRIDE);
        const float b1c = b1s[c];
        unsigned long long w1r[5];
#pragma unroll
        for (int k2 = 0; k2 < 5; k2++) w1r[k2] = w1p[k2];

        float ha[5], hb[5];
#pragma unroll
        for (int kk = 0; kk < 5; kk++) {
            unsigned long long sa = 0ULL, sb = 0ULL;
#pragma unroll
            for (int k2 = 0; k2 < 5; k2++) {
                fma2(sa, xra[kk * 5 + k2], w1r[k2], sa);
                fma2(sb, xrb[kk * 5 + k2], w1r[k2], sb);
            }
            float lo, hi;
            unpack2(sa, lo, hi); ha[kk] = fminf(fmaxf(lo + hi + b1c, 0.f), 6.f);
            unpack2(sb, lo, hi); hb[kk] = fminf(fmaxf(lo + hi + b1c, 0.f), 6.f);
        }
        const float* wrow = &W2s[c * W2STRIDE];
#pragma unroll
        for (int kk = 0; kk < 5; kk++) {
            const unsigned long long hpa = bcast2(ha[kk]);
            const unsigned long long hpb = bcast2(hb[kk]);
#pragma unroll
            for (int og = 0; og < 7; og++) {
                ulonglong2 w = *(const ulonglong2*)(wrow + kk * 28 + og * 4);
                fma2(acca[og * 2 + 0], hpa, w.x, acca[og * 2 + 0]);
                fma2(acca[og * 2 + 1], hpa, w.y, acca[og * 2 + 1]);
                fma2(accb[og * 2 + 0], hpb, w.x, accb[og * 2 + 0]);
                fma2(accb[og * 2 + 1], hpb, w.y, accb[og * 2 + 1]);
            }
        }
    }

    // reduce the 8 c-groups (lane bits 0..2), packed adds
#pragma unroll
    for (int j = 0; j < 14; j++) {
        unsigned long long v = acca[j], o;
        o = __shfl_xor_sync(0xffffffffu, v, 1); add2(v, v, o);
        o = __shfl_xor_sync(0xffffffffu, v, 2); add2(v, v, o);
        o = __shfl_xor_sync(0xffffffffu, v, 4); add2(v, v, o);
        acca[j] = v;
        unsigned long long u = accb[j], p;
        p = __shfl_xor_sync(0xffffffffu, u, 1); add2(u, u, p);
        p = __shfl_xor_sync(0xffffffffu, u, 2); add2(u, u, p);
        p = __shfl_xor_sync(0xffffffffu, u, 4); add2(u, u, p);
        accb[j] = u;
    }

    if (cg == 0) {
        float acc[28];
#pragma unroll
        for (int j = 0; j < 14; j++) unpack2(acca[j], acc[2 * j], acc[2 * j + 1]);
        {
            const float* g = gumbel + (b * TT + ta) * VV;
            float best = -1e30f; int bi = 0;
#pragma unroll
            for (int o = 0; o < 28; o++) {
                float v = acc[o] + b2s[o] + g[o];
                if (v > best) { best = v; bi = o; }
            }
            g_preds[b * TT + ta] = bi;
        }
#pragma unroll
        for (int j = 0; j < 14; j++) unpack2(accb[j], acc[2 * j], acc[2 * j + 1]);
        {
            const float* g = gumbel + (b * TT + ta + 1) * VV;
            float best = -1e30f; int bi = 0;
#pragma unroll
            for (int o = 0; o < 28; o++) {
                float v = acc[o] + b2s[o] + g[o];
                if (v > best) { best = v; bi = o; }
            }
            g_preds[b * TT + ta + 1] = bi;
        }
    }
}

// ---------------- decoder table: logprob[i][j2][j][q] ----------------
__global__ __launch_bounds__(256)
void k_table(const float* __restrict__ Wd1, const float* __restrict__ bd1,
             const float* __restrict__ bd2)
{
    __shared__ float rv[5 * 256];
    __shared__ float red[8];
    const int i   = blockIdx.x / 10;
    const int j   = blockIdx.x % 10;
    const int tid = threadIdx.x;

    for (int lin = tid; lin < 1280; lin += 256) {
        int c = lin / 5, j2 = lin % 5;
        float w = (i < VV) ? Wd1[i * 1280 + lin] : 0.f;
        rv[j2 * 256 + c] = fminf(fmaxf(w + bd1[c], 0.f), 6.f);
    }
    __syncthreads();

    float acc[5] = {0.f, 0.f, 0.f, 0.f, 0.f};
    const float* wt = g_Wd2T + j * 65536 + tid;
#pragma unroll 16
    for (int c = 0; c < 256; c++) {
        float w = wt[c * 256];
#pragma unroll
        for (int j2 = 0; j2 < 5; j2++)
            acc[j2] += rv[j2 * 256 + c] * w;
    }

    const float bdq  = bd2[tid];
    const int   lane = tid & 31, wid = tid >> 5;
    for (int j2 = 0; j2 < 5; j2++) {
        float v = acc[j2] + bdq;
        float m = v;
        for (int s = 16; s > 0; s >>= 1) m = fmaxf(m, __shfl_xor_sync(0xffffffffu, m, s));
        if (lane == 0) red[wid] = m;
        __syncthreads();
        float mAll = red[0];
#pragma unroll
        for (int w2 = 1; w2 < 8; w2++) mAll = fmaxf(mAll, red[w2]);
        __syncthreads();
        float e = expf(v - mAll);
        for (int s = 16; s > 0; s >>= 1) e += __shfl_xor_sync(0xffffffffu, e, s);
        if (lane == 0) red[wid] = e;
        __syncthreads();
        float ssum = 0.f;
#pragma unroll
        for (int w2 = 0; w2 < 8; w2++) ssum += red[w2];
        const float lse = mAll + logf(ssum);
        g_M[(((i * 5 + j2) * 10 + j) * 256) + tid] = v - lse;
        __syncthreads();
    }
}

// ---------------- loss (4 samples/thread) + fused final reduction ----------------
__global__ __launch_bounds__(256)
void k_loss(const float* __restrict__ x, const int* __restrict__ x_sl,
            const float* __restrict__ ngrams, float* __restrict__ out)
{
    __shared__ double sr[8], sk[8];
    __shared__ int    isLast;
    const int tid  = threadIdx.x;
    const int gid0 = (blockIdx.x * 256 + tid) * 4;      // < 384000
    const int b    = gid0 / LL;
    const int sl   = x_sl[b];
    const int zsl  = sl / 50;

    const float4 xv4 = *(const float4*)(x + gid0);
    const float xv[4] = {xv4.x, xv4.y, xv4.z, xv4.w};

    float rec = 0.f, kl = 0.f;
#pragma unroll
    for (int s = 0; s < 4; s++) {
        const int l = gid0 % LL + s;
        const int t = l / 50;
        if (l < sl) {
            float y = log1pf(255.f * fabsf(xv[s])) / 5.5451774444795625f;
            y = copysignf(y, xv[s]);
            int tq = (int)floorf((y + 1.0f) * 0.5f * 256.0f);
            tq = min(max(tq, 0), 255);
            const int j2 = (l / 10) % 5;
            const int j  = l % 10;
            const int i  = (t < zsl) ? g_preds[b * TT + t] : 28;
            rec -= g_M[(((i * 5 + j2) * 10 + j) * 256) + tq];
        }
        if ((l % 50) == 0 && t < zsl) {
            const int p  = g_preds[b * TT + t];
            const int a0 = (t >= 2) ? g_preds[b * TT + t - 2] : 28;
            const int a1 = (t >= 1) ? g_preds[b * TT + t - 1] : 28;
            const float pr = ngrams[(a0 * 29 + a1) * 28 + p];
            kl += logf(1.0f / (pr + 1e-10f) + 1e-10f);
        }
    }

    const int lane = tid & 31, wid = tid >> 5;
    for (int s = 16; s > 0; s >>= 1) {
        rec += __shfl_down_sync(0xffffffffu, rec, s);
        kl  += __shfl_down_sync(0xffffffffu, kl,  s);
    }
    if (lane == 0) { sr[wid] = (double)rec; sk[wid] = (double)kl; }
    __syncthreads();
    if (tid == 0) {
        double r = 0.0, k = 0.0;
#pragma unroll
        for (int w2 = 0; w2 < 8; w2++) { r += sr[w2]; k += sk[w2]; }
        g_prec[blockIdx.x] = r;
        g_pkl[blockIdx.x]  = k;
        __threadfence();
        int tck = atomicAdd(&g_ticket, 1);
        isLast = (tck == LOSS_BLOCKS - 1);
    }
    __syncthreads();

    if (isLast) {
        double r = 0.0, k = 0.0;
        for (int i = tid; i < LOSS_BLOCKS; i += 256) {
            r += __ldcg(&g_prec[i]);
            k += __ldcg(&g_pkl[i]);
        }
        for (int s = 16; s > 0; s >>= 1) {
            r += __shfl_down_sync(0xffffffffu, r, s);
            k += __shfl_down_sync(0xffffffffu, k, s);
        }
        __syncthreads();                 // sr/sk reuse
        if (lane == 0) { sr[wid] = r; sk[wid] = k; }
        __syncthreads();
        if (tid == 0) {
            double R = 0.0, K = 0.0;
#pragma unroll
            for (int w2 = 0; w2 < 8; w2++) { R += sr[w2]; K += sk[w2]; }
            long long sx = 0, sz = 0;
#pragma unroll
            for (int bb = 0; bb < BB; bb++) { sx += x_sl[bb]; sz += x_sl[bb] / 50; }
            out[0] = (float)(R / (double)sx + K / (double)sz);
            g_ticket = 0;               // self-reset for next graph replay
        }
    }
}

// ---------------- launch ----------------
extern "C" void kernel_launch(void* const* d_in, const int* in_sizes, int n_in,
                              void* d_out, int out_size)
{
    const float* x      = (const float*)d_in[0];
    const int*   x_sl   = (const int*)  d_in[1];
    const float* ngrams = (const float*)d_in[4];
    const float* gumbel = (const float*)d_in[5];
    const float* W1     = (const float*)d_in[6];
    const float* b1     = (const float*)d_in[7];
    const float* W2     = (const float*)d_in[8];
    const float* b2     = (const float*)d_in[9];
    const float* Wd1    = (const float*)d_in[10];
    const float* bd1    = (const float*)d_in[11];
    const float* Wd2    = (const float*)d_in[12];
    const float* bd2    = (const float*)d_in[13];
    float* out = (float*)d_out;

    cudaFuncSetAttribute(k_enc_tr, cudaFuncAttributeMaxDynamicSharedMemorySize,
                         ENC_SMEM_BYTES);

    k_enc_tr<<<ENC_BLOCKS + TR_BLOCKS, 256, ENC_SMEM_BYTES>>>(
        x, gumbel, W1, b1, W2, b2, Wd2);
    k_table<<<290, 256>>>(Wd1, bd1, bd2);
    k_loss<<<LOSS_BLOCKS, 256>>>(x, x_sl, ngrams, out);
}

// round 9
// speedup vs baseline: 1.3665x; 1.0026x over previous
#include <cuda_runtime.h>
#include <math.h>

#define BB 8
#define LL 48000
#define VV 28
#define QQ 256
#define CC 256
#define TT 960          // L / 50
#define NGD 29          // V + 1

#define ENC_BLOCKS 120          // 8 b * 15 chunks of 64 t
#define TR_BLOCKS  256
#define LOSS_BLOCKS 375         // 384000 / (256*4)

// ---------------- scratch ----------------
__device__ int    g_preds[BB * TT];
__device__ float  g_Wd2T[10 * 256 * 256];     // [j][c][q]
__device__ float  g_M[NGD * 5 * 10 * 256];    // logprob table: acc + bd2 - LSE
__device__ double g_prec[LOSS_BLOCKS];
__device__ double g_pkl[LOSS_BLOCKS];
__device__ int    g_ticket;                   // zero-init; self-resets each pass

// ---------------- f32x2 helpers ----------------
__device__ __forceinline__ void fma2(unsigned long long& d, unsigned long long a,
                                     unsigned long long b, unsigned long long c) {
    asm("fma.rn.f32x2 %0, %1, %2, %3;" : "=l"(d) : "l"(a), "l"(b), "l"(c));
}
__device__ __forceinline__ void add2(unsigned long long& d, unsigned long long a,
                                     unsigned long long b) {
    asm("add.rn.f32x2 %0, %1, %2;" : "=l"(d) : "l"(a), "l"(b));
}
__device__ __forceinline__ unsigned long long bcast2(float v) {
    unsigned long long r;
    asm("mov.b64 %0, {%1, %1};" : "=l"(r) : "f"(v));
    return r;
}
__device__ __forceinline__ void unpack2(unsigned long long v, float& lo, float& hi) {
    asm("mov.b64 {%0, %1}, %2;" : "=f"(lo), "=f"(hi) : "l"(v));
}

// ---------------- fused encoder + Wd2 transpose ----------------
// blocks [0,120): encoder, 64 t, 512 thr = 64 slots(1t) x 8 cg.
//   Pair-split: slot pairs (s, s^1) exchange conv1 h via shfl; each lane
//   accumulates conv2 for BOTH pair-t's but only its o-half (oh = s&1).
//   -> 16 warps/SM (4/SMSP) with round-8-level crossbar traffic.
// blocks [120,376): Wd2 transpose (C,Q,K1) -> [j][c][q], one c per block.
//
// W2s layout: [c][oh][kk][14 o'], c-stride 162 (=2 mod 32), oh-stride 80 (=16 mod 32):
// the 16 distinct (cg,oh) LDS.64 addresses per warp tile all 32 banks once.
#define W2STRIDE 162
#define W1STRIDE 14
#define ENC_T    64
#define W2S_OFF 0
#define W1S_OFF (256 * W2STRIDE)                    // 41472
#define XS_OFF  (W1S_OFF + 256 * W1STRIDE)          // +3584
#define B1S_OFF (XS_OFF + ENC_T * 50)               // +3200
#define B2S_OFF (B1S_OFF + 256)
#define LS_OFF  (B2S_OFF + 32)
#define ENC_SMEM_FLOATS (LS_OFF + ENC_T * 30)       // logits buffer 64x30
#define ENC_SMEM_BYTES  (ENC_SMEM_FLOATS * 4)

__global__ __launch_bounds__(512, 1)
void k_enc_tr(const float* __restrict__ x, const float* __restrict__ gumbel,
              const float* __restrict__ W1, const float* __restrict__ b1,
              const float* __restrict__ W2, const float* __restrict__ b2,
              const float* __restrict__ Wd2)
{
    extern __shared__ float sm[];
    const int tid = threadIdx.x;

    if (blockIdx.x >= ENC_BLOCKS) {
        // ----- transpose branch -----
        const int c = blockIdx.x - ENC_BLOCKS;
        float* tile = sm;
        for (int lin = tid; lin < 2560; lin += 512)
            tile[lin] = Wd2[c * 2560 + lin];        // coalesced read
        __syncthreads();
        if (tid < 256) {
            const int q = tid;
#pragma unroll
            for (int j = 0; j < 10; j++)
                g_Wd2T[j * 65536 + c * 256 + q] = tile[q * 10 + j];
        }
        return;
    }

    // ----- encoder branch -----
    float* W2s = sm + W2S_OFF;
    float* W1s = sm + W1S_OFF;
    float* xs  = sm + XS_OFF;
    float* b1s = sm + B1S_OFF;
    float* b2s = sm + B2S_OFF;
    float* ls  = sm + LS_OFF;

    const int b   = blockIdx.x / 15;
    const int t0  = (blockIdx.x % 15) * ENC_T;

    // stage W2 into [c][oh][kk][14] layout
    for (int lin = tid; lin < 28 * 256 * 5; lin += 512) {
        int o = lin / 1280, rem = lin % 1280;
        int c = rem / 5,    kk  = rem % 5;
        int oh = (o >= 14);
        int oo = o - 14 * oh;
        W2s[c * W2STRIDE + oh * 80 + kk * 14 + oo] = W2[lin];
    }
    for (int lin = tid; lin < 2560; lin += 512)
        W1s[(lin / 10) * W1STRIDE + (lin % 10)] = W1[lin];
    for (int lin = tid; lin < ENC_T * 50; lin += 512)
        xs[lin] = x[b * LL + t0 * 50 + lin];
    if (tid < 256) b1s[tid] = b1[tid];
    if (tid < 28)  b2s[tid] = b2[tid];
    __syncthreads();

    const int s   = tid >> 3;     // slot 0..63, one t each
    const int cg  = tid & 7;      // channel group
    const int oh  = s & 1;        // o-half this lane accumulates
    const int t   = t0 + s;       // own t (conv1)

    // own x window (50 floats, 8B aligned since 50*s is even)
    const unsigned long long* xsp = (const unsigned long long*)(xs + 50 * s);
    unsigned long long xr2[25];
#pragma unroll
    for (int j = 0; j < 25; j++) xr2[j] = xsp[j];

    // acc_e: pair's even t, acc_o: pair's odd t; 7 ull = 14 o (this lane's half)
    unsigned long long acc_e[7], acc_o[7];
#pragma unroll
    for (int j = 0; j < 7; j++) { acc_e[j] = 0ULL; acc_o[j] = 0ULL; }

    for (int ci = 0; ci < 32; ci++) {
        const int c = cg + 8 * ci;
        const unsigned long long* w1p = (const unsigned long long*)(W1s + c * W1STRIDE);
        const float b1c = b1s[c];

        // conv1 for own t
        float h_own[5];
#pragma unroll
        for (int kk = 0; kk < 5; kk++) {
            unsigned long long s2 = 0ULL;
#pragma unroll
            for (int k2 = 0; k2 < 5; k2++)
                fma2(s2, xr2[kk * 5 + k2], w1p[k2], s2);
            float lo, hi; unpack2(s2, lo, hi);
            h_own[kk] = fminf(fmaxf(lo + hi + b1c, 0.f), 6.f);
        }
        // exchange with pair partner (tid ^ 8)
        float h_oth[5];
#pragma unroll
        for (int kk = 0; kk < 5; kk++)
            h_oth[kk] = __shfl_xor_sync(0xffffffffu, h_own[kk], 8);

        // conv2: both pair t's, own o-half
        const unsigned long long* wrow =
            (const unsigned long long*)(W2s + c * W2STRIDE + oh * 80);
#pragma unroll
        for (int kk = 0; kk < 5; kk++) {
            const float he = oh ? h_oth[kk] : h_own[kk];   // even t of pair
            const float ho = oh ? h_own[kk] : h_oth[kk];   // odd  t of pair
            const unsigned long long hpe = bcast2(he);
            const unsigned long long hpo = bcast2(ho);
#pragma unroll
            for (int u = 0; u < 7; u++) {
                unsigned long long w = wrow[kk * 7 + u];
                fma2(acc_e[u], hpe, w, acc_e[u]);
                fma2(acc_o[u], hpo, w, acc_o[u]);
            }
        }
    }

    // reduce over the 8 c-groups (tid bits 0..2)
#pragma unroll
    for (int j = 0; j < 7; j++) {
        unsigned long long v = acc_e[j], o2;
        o2 = __shfl_xor_sync(0xffffffffu, v, 1); add2(v, v, o2);
        o2 = __shfl_xor_sync(0xffffffffu, v, 2); add2(v, v, o2);
        o2 = __shfl_xor_sync(0xffffffffu, v, 4); add2(v, v, o2);
        acc_e[j] = v;
        unsigned long long u2 = acc_o[j], p2;
        p2 = __shfl_xor_sync(0xffffffffu, u2, 1); add2(u2, u2, p2);
        p2 = __shfl_xor_sync(0xffffffffu, u2, 2); add2(u2, u2, p2);
        p2 = __shfl_xor_sync(0xffffffffu, u2, 4); add2(u2, u2, p2);
        acc_o[j] = u2;
    }

    // cg==0 lanes write their 14-o half for both pair t's
    if (cg == 0) {
        const int te = s & ~1;          // local even t of pair
        const int to = te + 1;
#pragma unroll
        for (int u = 0; u < 7; u++) {
            float lo, hi;
            unpack2(acc_e[u], lo, hi);
            ls[te * 30 + oh * 14 + 2 * u]     = lo;
            ls[te * 30 + oh * 14 + 2 * u + 1] = hi;
            unpack2(acc_o[u], lo, hi);
            ls[to * 30 + oh * 14 + 2 * u]     = lo;
            ls[to * 30 + oh * 14 + 2 * u + 1] = hi;
        }
    }
    __syncthreads();

    // argmax per t
    if (tid < ENC_T) {
        const int tg = t0 + tid;
        const float* g = gumbel + (b * TT + tg) * VV;
        const float* lrow = ls + tid * 30;
        float best = -1e30f; int bi = 0;
#pragma unroll
        for (int o = 0; o < 28; o++) {
            float v = lrow[o] + b2s[o] + g[o];
            if (v > best) { best = v; bi = o; }
        }
        g_preds[b * TT + tg] = bi;
    }
}

// ---------------- decoder table: logprob[i][j2][j][q] ----------------
__global__ __launch_bounds__(256)
void k_table(const float* __restrict__ Wd1, const float* __restrict__ bd1,
             const float* __restrict__ bd2)
{
    __shared__ float rv[5 * 256];
    __shared__ float red[8];
    const int i   = blockIdx.x / 10;
    const int j   = blockIdx.x % 10;
    const int tid = threadIdx.x;

    for (int lin = tid; lin < 1280; lin += 256) {
        int c = lin / 5, j2 = lin % 5;
        float w = (i < VV) ? Wd1[i * 1280 + lin] : 0.f;
        rv[j2 * 256 + c] = fminf(fmaxf(w + bd1[c], 0.f), 6.f);
    }
    __syncthreads();

    float acc[5] = {0.f, 0.f, 0.f, 0.f, 0.f};
    const float* wt = g_Wd2T + j * 65536 + tid;
#pragma unroll 16
    for (int c = 0; c < 256; c++) {
        float w = wt[c * 256];
#pragma unroll
        for (int j2 = 0; j2 < 5; j2++)
            acc[j2] += rv[j2 * 256 + c] * w;
    }

    const float bdq  = bd2[tid];
    const int   lane = tid & 31, wid = tid >> 5;
    for (int j2 = 0; j2 < 5; j2++) {
        float v = acc[j2] + bdq;
        float m = v;
        for (int s = 16; s > 0; s >>= 1) m = fmaxf(m, __shfl_xor_sync(0xffffffffu, m, s));
        if (lane == 0) red[wid] = m;
        __syncthreads();
        float mAll = red[0];
#pragma unroll
        for (int w2 = 1; w2 < 8; w2++) mAll = fmaxf(mAll, red[w2]);
        __syncthreads();
        float e = expf(v - mAll);
        for (int s = 16; s > 0; s >>= 1) e += __shfl_xor_sync(0xffffffffu, e, s);
        if (lane == 0) red[wid] = e;
        __syncthreads();
        float ssum = 0.f;
#pragma unroll
        for (int w2 = 0; w2 < 8; w2++) ssum += red[w2];
        const float lse = mAll + logf(ssum);
        g_M[(((i * 5 + j2) * 10 + j) * 256) + tid] = v - lse;
        __syncthreads();
    }
}

// ---------------- loss (4 samples/thread) + fused final reduction ----------------
__global__ __launch_bounds__(256)
void k_loss(const float* __restrict__ x, const int* __restrict__ x_sl,
            const float* __restrict__ ngrams, float* __restrict__ out)
{
    __shared__ double sr[8], sk[8];
    __shared__ int    isLast;
    const int tid  = threadIdx.x;
    const int gid0 = (blockIdx.x * 256 + tid) * 4;      // < 384000
    const int b    = gid0 / LL;
    const int sl   = x_sl[b];
    const int zsl  = sl / 50;

    const float4 xv4 = *(const float4*)(x + gid0);
    const float xv[4] = {xv4.x, xv4.y, xv4.z, xv4.w};

    float rec = 0.f, kl = 0.f;
#pragma unroll
    for (int s = 0; s < 4; s++) {
        const int l = gid0 % LL + s;
        const int t = l / 50;
        if (l < sl) {
            float y = log1pf(255.f * fabsf(xv[s])) / 5.5451774444795625f;
            y = copysignf(y, xv[s]);
            int tq = (int)floorf((y + 1.0f) * 0.5f * 256.0f);
            tq = min(max(tq, 0), 255);
            const int j2 = (l / 10) % 5;
            const int j  = l % 10;
            const int i  = (t < zsl) ? g_preds[b * TT + t] : 28;
            rec -= g_M[(((i * 5 + j2) * 10 + j) * 256) + tq];
        }
        if ((l % 50) == 0 && t < zsl) {
            const int p  = g_preds[b * TT + t];
            const int a0 = (t >= 2) ? g_preds[b * TT + t - 2] : 28;
            const int a1 = (t >= 1) ? g_preds[b * TT + t - 1] : 28;
            const float pr = ngrams[(a0 * 29 + a1) * 28 + p];
            kl += logf(1.0f / (pr + 1e-10f) + 1e-10f);
        }
    }

    const int lane = tid & 31, wid = tid >> 5;
    for (int s = 16; s > 0; s >>= 1) {
        rec += __shfl_down_sync(0xffffffffu, rec, s);
        kl  += __shfl_down_sync(0xffffffffu, kl,  s);
    }
    if (lane == 0) { sr[wid] = (double)rec; sk[wid] = (double)kl; }
    __syncthreads();
    if (tid == 0) {
        double r = 0.0, k = 0.0;
#pragma unroll
        for (int w2 = 0; w2 < 8; w2++) { r += sr[w2]; k += sk[w2]; }
        g_prec[blockIdx.x] = r;
        g_pkl[blockIdx.x]  = k;
        __threadfence();
        int tck = atomicAdd(&g_ticket, 1);
        isLast = (tck == LOSS_BLOCKS - 1);
    }
    __syncthreads();

    if (isLast) {
        double r = 0.0, k = 0.0;
        for (int i = tid; i < LOSS_BLOCKS; i += 256) {
            r += __ldcg(&g_prec[i]);
            k += __ldcg(&g_pkl[i]);
        }
        for (int s = 16; s > 0; s >>= 1) {
            r += __shfl_down_sync(0xffffffffu, r, s);
            k += __shfl_down_sync(0xffffffffu, k, s);
        }
        __syncthreads();
        if (lane == 0) { sr[wid] = r; sk[wid] = k; }
        __syncthreads();
        if (tid == 0) {
            double R = 0.0, K = 0.0;
#pragma unroll
            for (int w2 = 0; w2 < 8; w2++) { R += sr[w2]; K += sk[w2]; }
            long long sx = 0, sz = 0;
#pragma unroll
            for (int bb = 0; bb < BB; bb++) { sx += x_sl[bb]; sz += x_sl[bb] / 50; }
            out[0] = (float)(R / (double)sx + K / (double)sz);
            g_ticket = 0;               // self-reset for next graph replay
        }
    }
}

// ---------------- launch ----------------
extern "C" void kernel_launch(void* const* d_in, const int* in_sizes, int n_in,
                              void* d_out, int out_size)
{
    const float* x      = (const float*)d_in[0];
    const int*   x_sl   = (const int*)  d_in[1];
    const float* ngrams = (const float*)d_in[4];
    const float* gumbel = (const float*)d_in[5];
    const float* W1     = (const float*)d_in[6];
    const float* b1     = (const float*)d_in[7];
    const float* W2     = (const float*)d_in[8];
    const float* b2     = (const float*)d_in[9];
    const float* Wd1    = (const float*)d_in[10];
    const float* bd1    = (const float*)d_in[11];
    const float* Wd2    = (const float*)d_in[12];
    const float* bd2    = (const float*)d_in[13];
    float* out = (float*)d_out;

    cudaFuncSetAttribute(k_enc_tr, cudaFuncAttributeMaxDynamicSharedMemorySize,
                         ENC_SMEM_BYTES);

    k_enc_tr<<<ENC_BLOCKS + TR_BLOCKS, 512, ENC_SMEM_BYTES>>>(
        x, gumbel, W1, b1, W2, b2, Wd2);
    k_table<<<290, 256>>>(Wd1, bd1, bd2);
    k_loss<<<LOSS_BLOCKS, 256>>>(x, x_sl, ngrams, out);
}

// round 13
// speedup vs baseline: 1.4025x; 1.0263x over previous
#include <cuda_runtime.h>
#include <math.h>

#define BB 8
#define LL 48000
#define VV 28
#define QQ 256
#define CC 256
#define TT 960          // L / 50
#define NGD 29          // V + 1

#define ENC_BLOCKS 120          // 8 b * 15 chunks of 64 t
#define TR_BLOCKS  256
#define LOSS_BLOCKS 375         // 384000 / (256*4)

// ---------------- scratch ----------------
__device__ int    g_preds[BB * TT];
__device__ float  g_Wd2T[10 * 256 * 256];     // [j][c][q]
__device__ float  g_M[NGD * 5 * 10 * 256];    // logprob table: acc + bd2 - LSE
__device__ double g_prec[LOSS_BLOCKS];
__device__ double g_pkl[LOSS_BLOCKS];
__device__ int    g_ticket;                   // zero-init; self-resets each pass

// ---------------- f32x2 helpers ----------------
__device__ __forceinline__ void fma2(unsigned long long& d, unsigned long long a,
                                     unsigned long long b, unsigned long long c) {
    asm("fma.rn.f32x2 %0, %1, %2, %3;" : "=l"(d) : "l"(a), "l"(b), "l"(c));
}
__device__ __forceinline__ void add2(unsigned long long& d, unsigned long long a,
                                     unsigned long long b) {
    asm("add.rn.f32x2 %0, %1, %2;" : "=l"(d) : "l"(a), "l"(b));
}
__device__ __forceinline__ unsigned long long bcast2(float v) {
    unsigned long long r;
    asm("mov.b64 %0, {%1, %1};" : "=l"(r) : "f"(v));
    return r;
}
__device__ __forceinline__ void unpack2(unsigned long long v, float& lo, float& hi) {
    asm("mov.b64 {%0, %1}, %2;" : "=f"(lo), "=f"(hi) : "l"(v));
}

// ---------------- fused encoder + Wd2 transpose ----------------
// blocks [0,120): encoder, 64 t, 512 thr = 64 slots(1t) x 8 cg.
//   Quarter-split: warp = 8 cg x 4 slots; slot q owns o-quarter q (8 outputs,
//   28 padded to 32). All 32 lanes load DISTINCT W2 data (no crossbar dup).
//   h exchanged across the 4 slots via butterfly shfl (xor 8, xor 16);
//   each lane accumulates its quarter for all 4 slot-group t's.
// blocks [120,376): Wd2 transpose (C,Q,K1) -> [j][c][q], one c per block.
//
// W2s layout [c][q][kk][8o]: c-stride 164 (=4 mod 32), q-stride 40 (=8 mod 32)
// -> each LDS.128 quarter-warp phase tiles all 32 banks exactly once.
#define W2STRIDE 164
#define W1STRIDE 14
#define ENC_T    64
#define LSTRIDE  33
#define W2S_OFF 0
#define W1S_OFF (256 * W2STRIDE)                    // 41984
#define XS_OFF  (W1S_OFF + 256 * W1STRIDE)
#define B1S_OFF (XS_OFF + ENC_T * 50)
#define B2S_OFF (B1S_OFF + 256)
#define LS_OFF  (B2S_OFF + 32)
#define ENC_SMEM_FLOATS (LS_OFF + ENC_T * LSTRIDE)
#define ENC_SMEM_BYTES  (ENC_SMEM_FLOATS * 4)       // ~204.7 KB

__global__ __launch_bounds__(512, 1)
void k_enc_tr(const float* __restrict__ x, const float* __restrict__ gumbel,
              const float* __restrict__ W1, const float* __restrict__ b1,
              const float* __restrict__ W2, const float* __restrict__ b2,
              const float* __restrict__ Wd2)
{
    extern __shared__ float sm[];
    const int tid = threadIdx.x;

    if (blockIdx.x >= ENC_BLOCKS) {
        // ----- transpose branch -----
        const int c = blockIdx.x - ENC_BLOCKS;
        float* tile = sm;
        for (int lin = tid; lin < 2560; lin += 512)
            tile[lin] = Wd2[c * 2560 + lin];        // coalesced read
        __syncthreads();
        if (tid < 256) {
            const int q = tid;
#pragma unroll
            for (int j = 0; j < 10; j++)
                g_Wd2T[j * 65536 + c * 256 + q] = tile[q * 10 + j];
        }
        return;
    }

    // ----- encoder branch -----
    float* W2s = sm + W2S_OFF;
    float* W1s = sm + W1S_OFF;
    float* xs  = sm + XS_OFF;
    float* b1s = sm + B1S_OFF;
    float* b2s = sm + B2S_OFF;
    float* ls  = sm + LS_OFF;

    const int b   = blockIdx.x / 15;
    const int t0  = (blockIdx.x % 15) * ENC_T;

    // stage W2 into [c][quarter][kk][8] layout (o padded 28 -> 32)
    for (int lin = tid; lin < 28 * 256 * 5; lin += 512) {
        int o = lin / 1280, rem = lin % 1280;
        int c = rem / 5,    kk  = rem % 5;
        int q = o >> 3, oo = o & 7;
        W2s[c * W2STRIDE + q * 40 + kk * 8 + oo] = W2[lin];
    }
    // zero the pad (quarter 3, oo 4..7)
    for (int lin = tid; lin < 256 * 5 * 4; lin += 512) {
        int c = lin / 20, kk = (lin % 20) / 4, oo = (lin % 4) + 4;
        W2s[c * W2STRIDE + 120 + kk * 8 + oo] = 0.f;
    }
    for (int lin = tid; lin < 2560; lin += 512)
        W1s[(lin / 10) * W1STRIDE + (lin % 10)] = W1[lin];
    for (int lin = tid; lin < ENC_T * 50; lin += 512)
        xs[lin] = x[b * LL + t0 * 50 + lin];
    if (tid < 256) b1s[tid] = b1[tid];
    if (tid < 28)  b2s[tid] = b2[tid];
    __syncthreads();

    const int s   = tid >> 3;     // slot 0..63, one t each
    const int cg  = tid & 7;      // channel group
    const int oq  = s & 3;        // o-quarter this lane accumulates

    // own x window (50 floats, even float offset -> 8B aligned)
    const unsigned long long* xsp = (const unsigned long long*)(xs + 50 * s);
    unsigned long long xr2[25];
#pragma unroll
    for (int j = 0; j < 25; j++) xr2[j] = xsp[j];

    // acc[r][u]: r = slot-exchange role (0:own, 1:^8, 2:^16, 3:^24), u = o-pair
    unsigned long long acc[4][4];
#pragma unroll
    for (int r = 0; r < 4; r++)
#pragma unroll
        for (int u = 0; u < 4; u++) acc[r][u] = 0ULL;

    for (int ci = 0; ci < 32; ci++) {
        const int c = cg + 8 * ci;
        const unsigned long long* w1p = (const unsigned long long*)(W1s + c * W1STRIDE);
        const float b1c = b1s[c];
        const float* wq = W2s + c * W2STRIDE + oq * 40;

#pragma unroll
        for (int kk = 0; kk < 5; kk++) {
            // conv1 for own t
            unsigned long long s2 = 0ULL;
#pragma unroll
            for (int k2 = 0; k2 < 5; k2++)
                fma2(s2, xr2[kk * 5 + k2], w1p[k2], s2);
            float lo, hi; unpack2(s2, lo, hi);
            const float h0 = fminf(fmaxf(lo + hi + b1c, 0.f), 6.f);
            // butterfly exchange across the 4 slots of the group
            const float h1 = __shfl_xor_sync(0xffffffffu, h0, 8);
            const float h2 = __shfl_xor_sync(0xffffffffu, h0, 16);
            const float h3 = __shfl_xor_sync(0xffffffffu, h1, 16);

            const ulonglong2* wp = (const ulonglong2*)(wq + kk * 8);
            const ulonglong2 w01 = wp[0];
            const ulonglong2 w23 = wp[1];

            const unsigned long long hp0 = bcast2(h0);
            const unsigned long long hp1 = bcast2(h1);
            const unsigned long long hp2 = bcast2(h2);
            const unsigned long long hp3 = bcast2(h3);

            fma2(acc[0][0], hp0, w01.x, acc[0][0]);
            fma2(acc[0][1], hp0, w01.y, acc[0][1]);
            fma2(acc[0][2], hp0, w23.x, acc[0][2]);
            fma2(acc[0][3], hp0, w23.y, acc[0][3]);
            fma2(acc[1][0], hp1, w01.x, acc[1][0]);
            fma2(acc[1][1], hp1, w01.y, acc[1][1]);
            fma2(acc[1][2], hp1, w23.x, acc[1][2]);
            fma2(acc[1][3], hp1, w23.y, acc[1][3]);
            fma2(acc[2][0], hp2, w01.x, acc[2][0]);
            fma2(acc[2][1], hp2, w01.y, acc[2][1]);
            fma2(acc[2][2], hp2, w23.x, acc[2][2]);
            fma2(acc[2][3], hp2, w23.y, acc[2][3]);
            fma2(acc[3][0], hp3, w01.x, acc[3][0]);
            fma2(acc[3][1], hp3, w01.y, acc[3][1]);
            fma2(acc[3][2], hp3, w23.x, acc[3][2]);
            fma2(acc[3][3], hp3, w23.y, acc[3][3]);
        }
    }

    // reduce over the 8 c-groups (tid bits 0..2)
#pragma unroll
    for (int r = 0; r < 4; r++)
#pragma unroll
        for (int u = 0; u < 4; u++) {
            unsigned long long v = acc[r][u], o2;
            o2 = __shfl_xor_sync(0xffffffffu, v, 1); add2(v, v, o2);
            o2 = __shfl_xor_sync(0xffffffffu, v, 2); add2(v, v, o2);
            o2 = __shfl_xor_sync(0xffffffffu, v, 4); add2(v, v, o2);
            acc[r][u] = v;
        }

    // cg==0 lanes write their 8-o quarter for all 4 slot-group t's
    if (cg == 0) {
        const int sbase = s & ~3;
#pragma unroll
        for (int r = 0; r < 4; r++) {
            const int tloc = sbase + ((s & 3) ^ r);   // role r -> local t
            float* lrow = ls + tloc * LSTRIDE + oq * 8;
#pragma unroll
            for (int u = 0; u < 4; u++) {
                float lo, hi; unpack2(acc[r][u], lo, hi);
                lrow[2 * u]     = lo;
                lrow[2 * u + 1] = hi;
            }
        }
    }
    __syncthreads();

    // argmax per t (stride 33 -> conflict-reduced)
    if (tid < ENC_T) {
        const int tg = t0 + tid;
        const float* g = gumbel + (b * TT + tg) * VV;
        const float* lrow = ls + tid * LSTRIDE;
        float best = -1e30f; int bi = 0;
#pragma unroll
        for (int o = 0; o < 28; o++) {
            float v = lrow[o] + b2s[o] + g[o];
            if (v > best) { best = v; bi = o; }
        }
        g_preds[b * TT + tg] = bi;
    }
}

// ---------------- decoder table: logprob[i][j2][j][q] ----------------
__global__ __launch_bounds__(256)
void k_table(const float* __restrict__ Wd1, const float* __restrict__ bd1,
             const float* __restrict__ bd2)
{
    __shared__ float rv[5 * 256];
    __shared__ float red[8];
    const int i   = blockIdx.x / 10;
    const int j   = blockIdx.x % 10;
    const int tid = threadIdx.x;

    for (int lin = tid; lin < 1280; lin += 256) {
        int c = lin / 5, j2 = lin % 5;
        float w = (i < VV) ? Wd1[i * 1280 + lin] : 0.f;
        rv[j2 * 256 + c] = fminf(fmaxf(w + bd1[c], 0.f), 6.f);
    }
    __syncthreads();

    float acc[5] = {0.f, 0.f, 0.f, 0.f, 0.f};
    const float* wt = g_Wd2T + j * 65536 + tid;
#pragma unroll 16
    for (int c = 0; c < 256; c++) {
        float w = wt[c * 256];
#pragma unroll
        for (int j2 = 0; j2 < 5; j2++)
            acc[j2] += rv[j2 * 256 + c] * w;
    }

    const float bdq  = bd2[tid];
    const int   lane = tid & 31, wid = tid >> 5;
    for (int j2 = 0; j2 < 5; j2++) {
        float v = acc[j2] + bdq;
        float m = v;
        for (int s = 16; s > 0; s >>= 1) m = fmaxf(m, __shfl_xor_sync(0xffffffffu, m, s));
        if (lane == 0) red[wid] = m;
        __syncthreads();
        float mAll = red[0];
#pragma unroll
        for (int w2 = 1; w2 < 8; w2++) mAll = fmaxf(mAll, red[w2]);
        __syncthreads();
        float e = expf(v - mAll);
        for (int s = 16; s > 0; s >>= 1) e += __shfl_xor_sync(0xffffffffu, e, s);
        if (lane == 0) red[wid] = e;
        __syncthreads();
        float ssum = 0.f;
#pragma unroll
        for (int w2 = 0; w2 < 8; w2++) ssum += red[w2];
        const float lse = mAll + logf(ssum);
        g_M[(((i * 5 + j2) * 10 + j) * 256) + tid] = v - lse;
        __syncthreads();
    }
}

// ---------------- loss (4 samples/thread) + fused final reduction ----------------
__global__ __launch_bounds__(256)
void k_loss(const float* __restrict__ x, const int* __restrict__ x_sl,
            const float* __restrict__ ngrams, float* __restrict__ out)
{
    __shared__ double sr[8], sk[8];
    __shared__ int    isLast;
    const int tid  = threadIdx.x;
    const int gid0 = (blockIdx.x * 256 + tid) * 4;      // < 384000
    const int b    = gid0 / LL;
    const int sl   = x_sl[b];
    const int zsl  = sl / 50;

    const float4 xv4 = *(const float4*)(x + gid0);
    const float xv[4] = {xv4.x, xv4.y, xv4.z, xv4.w};

    float rec = 0.f, kl = 0.f;
#pragma unroll
    for (int s = 0; s < 4; s++) {
        const int l = gid0 % LL + s;
        const int t = l / 50;
        if (l < sl) {
            float y = log1pf(255.f * fabsf(xv[s])) / 5.5451774444795625f;
            y = copysignf(y, xv[s]);
            int tq = (int)floorf((y + 1.0f) * 0.5f * 256.0f);
            tq = min(max(tq, 0), 255);
            const int j2 = (l / 10) % 5;
            const int j  = l % 10;
            const int i  = (t < zsl) ? g_preds[b * TT + t] : 28;
            rec -= g_M[(((i * 5 + j2) * 10 + j) * 256) + tq];
        }
        if ((l % 50) == 0 && t < zsl) {
            const int p  = g_preds[b * TT + t];
            const int a0 = (t >= 2) ? g_preds[b * TT + t - 2] : 28;
            const int a1 = (t >= 1) ? g_preds[b * TT + t - 1] : 28;
            const float pr = ngrams[(a0 * 29 + a1) * 28 + p];
            kl += logf(1.0f / (pr + 1e-10f) + 1e-10f);
        }
    }

    const int lane = tid & 31, wid = tid >> 5;
    for (int s = 16; s > 0; s >>= 1) {
        rec += __shfl_down_sync(0xffffffffu, rec, s);
        kl  += __shfl_down_sync(0xffffffffu, kl,  s);
    }
    if (lane == 0) { sr[wid] = (double)rec; sk[wid] = (double)kl; }
    __syncthreads();
    if (tid == 0) {
        double r = 0.0, k = 0.0;
#pragma unroll
        for (int w2 = 0; w2 < 8; w2++) { r += sr[w2]; k += sk[w2]; }
        g_prec[blockIdx.x] = r;
        g_pkl[blockIdx.x]  = k;
        __threadfence();
        int tck = atomicAdd(&g_ticket, 1);
        isLast = (tck == LOSS_BLOCKS - 1);
    }
    __syncthreads();

    if (isLast) {
        double r = 0.0, k = 0.0;
        for (int i = tid; i < LOSS_BLOCKS; i += 256) {
            r += __ldcg(&g_prec[i]);
            k += __ldcg(&g_pkl[i]);
        }
        for (int s = 16; s > 0; s >>= 1) {
            r += __shfl_down_sync(0xffffffffu, r, s);
            k += __shfl_down_sync(0xffffffffu, k, s);
        }
        __syncthreads();
        if (lane == 0) { sr[wid] = r; sk[wid] = k; }
        __syncthreads();
        if (tid == 0) {
            double R = 0.0, K = 0.0;
#pragma unroll
            for (int w2 = 0; w2 < 8; w2++) { R += sr[w2]; K += sk[w2]; }
            long long sx = 0, sz = 0;
#pragma unroll
            for (int bb = 0; bb < BB; bb++) { sx += x_sl[bb]; sz += x_sl[bb] / 50; }
            out[0] = (float)(R / (double)sx + K / (double)sz);
            g_ticket = 0;               // self-reset for next graph replay
        }
    }
}

// ---------------- launch ----------------
extern "C" void kernel_launch(void* const* d_in, const int* in_sizes, int n_in,
                              void* d_out, int out_size)
{
    const float* x      = (const float*)d_in[0];
    const int*   x_sl   = (const int*)  d_in[1];
    const float* ngrams = (const float*)d_in[4];
    const float* gumbel = (const float*)d_in[5];
    const float* W1     = (const float*)d_in[6];
    const float* b1     = (const float*)d_in[7];
    const float* W2     = (const float*)d_in[8];
    const float* b2     = (const float*)d_in[9];
    const float* Wd1    = (const float*)d_in[10];
    const float* bd1    = (const float*)d_in[11];
    const float* Wd2    = (const float*)d_in[12];
    const float* bd2    = (const float*)d_in[13];
    float* out = (float*)d_out;

    cudaFuncSetAttribute(k_enc_tr, cudaFuncAttributeMaxDynamicSharedMemorySize,
                         ENC_SMEM_BYTES);

    k_enc_tr<<<ENC_BLOCKS + TR_BLOCKS, 512, ENC_SMEM_BYTES>>>(
        x, gumbel, W1, b1, W2, b2, Wd2);
    k_table<<<290, 256>>>(Wd1, bd1, bd2);
    k_loss<<<LOSS_BLOCKS, 256>>>(x, x_sl, ngrams, out);
}